// round 2
// baseline (speedup 1.0000x reference)
#include <cuda_runtime.h>
#include <cuda_bf16.h>
#include <math.h>

#define B_ 2
#define S_ 4096
#define D_ 512
#define H_ 8
#define DK_ 64
#define MROWS (B_ * S_)   // 8192

// ---------------- scratch (no allocations allowed) ----------------
__device__ float g_Q[MROWS * D_];
__device__ float g_K[MROWS * D_];
__device__ float g_V[MROWS * D_];
__device__ float g_AO[MROWS * D_];

// ---------------- GEMM: C[M,512] = A[M,512] @ W[512,512]^T ----------------
// 64x64 block tile, 256 threads, 4x4 microtile, BK=16
#define GBM 64
#define GBN 64
#define GBK 16

__device__ __forceinline__ void gemm_tile(const float* __restrict__ A,
                                          const float* __restrict__ W,
                                          float* __restrict__ C) {
    __shared__ float As[GBM][GBK + 1];
    __shared__ float Ws[GBN][GBK + 1];

    const int tid = threadIdx.x;
    const int tx = tid & 15;
    const int ty = tid >> 4;
    const int m0 = blockIdx.x * GBM;
    const int n0 = blockIdx.y * GBN;

    float acc[4][4] = {};

    for (int k0 = 0; k0 < D_; k0 += GBK) {
#pragma unroll
        for (int i = 0; i < 4; i++) {
            int e = tid + i * 256;
            int r = e >> 4, c = e & 15;
            As[r][c] = A[(m0 + r) * D_ + k0 + c];
            Ws[r][c] = W[(n0 + r) * D_ + k0 + c];
        }
        __syncthreads();
#pragma unroll
        for (int k = 0; k < GBK; k++) {
            float a[4], w[4];
#pragma unroll
            for (int r = 0; r < 4; r++) a[r] = As[ty * 4 + r][k];
#pragma unroll
            for (int c = 0; c < 4; c++) w[c] = Ws[tx * 4 + c][k];
#pragma unroll
            for (int r = 0; r < 4; r++)
#pragma unroll
                for (int c = 0; c < 4; c++) acc[r][c] += a[r] * w[c];
        }
        __syncthreads();
    }

#pragma unroll
    for (int r = 0; r < 4; r++)
#pragma unroll
        for (int c = 0; c < 4; c++)
            C[(m0 + ty * 4 + r) * D_ + n0 + tx * 4 + c] = acc[r][c];
}

// Fused Q/K/V projection: blockIdx.z selects which projection.
__global__ void proj_qkv_kernel(const float* __restrict__ q,
                                const float* __restrict__ k,
                                const float* __restrict__ v,
                                const float* __restrict__ wq,
                                const float* __restrict__ wk,
                                const float* __restrict__ wv) {
    int z = blockIdx.z;
    const float* A = (z == 0) ? q : (z == 1) ? k : v;
    const float* W = (z == 0) ? wq : (z == 1) ? wk : wv;
    float* C = (z == 0) ? g_Q : (z == 1) ? g_K : g_V;
    gemm_tile(A, W, C);
}

__global__ void proj_out_kernel(const float* __restrict__ wo,
                                float* __restrict__ out) {
    gemm_tile(g_AO, wo, out);
}

// ---------------- Flash attention (fp32, online softmax) ----------------
// grid: (S/64, B*H), block: 256 threads (16x16), 64x64 q/k tiles.
// Dynamic smem layout:
//   Qs[64][64]      (4096 f)
//   KsPs[64][65]    (4160 f)  K tile, reused as P tile
//   Vs[64][64]      (4096 f)
//   msk[64]         (64 i)
#define FSM_FLOATS (4096 + 4160 + 4096)
#define FSM_BYTES  (FSM_FLOATS * 4 + 64 * 4)

__global__ void flash_attn_kernel(const int* __restrict__ mask) {
    extern __shared__ float sm[];
    float* Qs = sm;                 // stride 64
    float* KsPs = sm + 4096;        // stride 65
    float* Vs = sm + 4096 + 4160;   // stride 64
    int* msk = (int*)(sm + FSM_FLOATS);

    const int tid = threadIdx.x;
    const int tx = tid & 15;
    const int ty = tid >> 4;
    const int bh = blockIdx.y;
    const int b = bh >> 3;
    const int h = bh & 7;
    const int qm0 = blockIdx.x * 64;
    const float scale = 0.125f;  // 1/sqrt(64)

    const float* Qb = g_Q + (b * S_ + qm0) * D_ + h * DK_;

    // load Q tile (64x64)
#pragma unroll
    for (int i = 0; i < 16; i++) {
        int e = tid + i * 256;
        int r = e >> 6, c = e & 63;
        Qs[r * 64 + c] = Qb[r * D_ + c];
    }

    float m_r[4], l_r[4], o[4][4] = {};
#pragma unroll
    for (int r = 0; r < 4; r++) { m_r[r] = -1e30f; l_r[r] = 0.0f; }

    for (int kn0 = 0; kn0 < S_; kn0 += 64) {
        const float* Kb = g_K + (b * S_ + kn0) * D_ + h * DK_;
        const float* Vb = g_V + (b * S_ + kn0) * D_ + h * DK_;

        __syncthreads();  // previous iteration's readers of KsPs/Vs done
#pragma unroll
        for (int i = 0; i < 16; i++) {
            int e = tid + i * 256;
            int r = e >> 6, c = e & 63;
            KsPs[r * 65 + c] = Kb[r * D_ + c];
            Vs[r * 64 + c] = Vb[r * D_ + c];
        }
        if (tid < 64) msk[tid] = mask[b * S_ + kn0 + tid];
        __syncthreads();

        // scores S = Q K^T  (4x4 per thread)
        float s[4][4] = {};
#pragma unroll 4
        for (int d = 0; d < 64; d++) {
            float a[4], kk[4];
#pragma unroll
            for (int r = 0; r < 4; r++) a[r] = Qs[(ty * 4 + r) * 64 + d];
#pragma unroll
            for (int c = 0; c < 4; c++) kk[c] = KsPs[(tx * 4 + c) * 65 + d];
#pragma unroll
            for (int r = 0; r < 4; r++)
#pragma unroll
                for (int c = 0; c < 4; c++) s[r][c] += a[r] * kk[c];
        }

        int mk[4];
#pragma unroll
        for (int c = 0; c < 4; c++) mk[c] = msk[tx * 4 + c];
#pragma unroll
        for (int r = 0; r < 4; r++)
#pragma unroll
            for (int c = 0; c < 4; c++)
                s[r][c] = mk[c] ? s[r][c] * scale : -1e30f;

        // row max across the 16 tx lanes
        float mnew[4], alpha[4];
#pragma unroll
        for (int r = 0; r < 4; r++) {
            float tm = fmaxf(fmaxf(s[r][0], s[r][1]), fmaxf(s[r][2], s[r][3]));
#pragma unroll
            for (int off = 1; off < 16; off <<= 1)
                tm = fmaxf(tm, __shfl_xor_sync(0xffffffffu, tm, off));
            mnew[r] = fmaxf(m_r[r], tm);
            alpha[r] = __expf(m_r[r] - mnew[r]);
            m_r[r] = mnew[r];
        }

        __syncthreads();  // everyone done reading K from KsPs

        // P = exp(S - m), write into KsPs (reused), accumulate row sums
        float rs[4] = {};
#pragma unroll
        for (int r = 0; r < 4; r++) {
#pragma unroll
            for (int c = 0; c < 4; c++) {
                float p = mk[c] ? __expf(s[r][c] - mnew[r]) : 0.0f;
                KsPs[(ty * 4 + r) * 65 + tx * 4 + c] = p;
                rs[r] += p;
            }
        }
#pragma unroll
        for (int r = 0; r < 4; r++) {
#pragma unroll
            for (int off = 1; off < 16; off <<= 1)
                rs[r] += __shfl_xor_sync(0xffffffffu, rs[r], off);
            l_r[r] = l_r[r] * alpha[r] + rs[r];
#pragma unroll
            for (int c = 0; c < 4; c++) o[r][c] *= alpha[r];
        }

        __syncthreads();  // P tile complete

        // O += P @ V
#pragma unroll 4
        for (int j = 0; j < 64; j++) {
            float p[4], v[4];
#pragma unroll
            for (int r = 0; r < 4; r++) p[r] = KsPs[(ty * 4 + r) * 65 + j];
#pragma unroll
            for (int c = 0; c < 4; c++) v[c] = Vs[j * 64 + tx * 4 + c];
#pragma unroll
            for (int r = 0; r < 4; r++)
#pragma unroll
                for (int c = 0; c < 4; c++) o[r][c] += p[r] * v[c];
        }
    }

    // normalize and write (fully-masked rows -> 0, matching nan_to_num)
    float* Ob = g_AO + (b * S_ + qm0) * D_ + h * DK_;
#pragma unroll
    for (int r = 0; r < 4; r++) {
        float inv = (l_r[r] > 0.0f) ? (1.0f / l_r[r]) : 0.0f;
#pragma unroll
        for (int c = 0; c < 4; c++)
            Ob[(ty * 4 + r) * D_ + tx * 4 + c] = o[r][c] * inv;
    }
}

// ---------------- launch ----------------
extern "C" void kernel_launch(void* const* d_in, const int* in_sizes, int n_in,
                              void* d_out, int out_size) {
    const float* q  = (const float*)d_in[0];
    const float* k  = (const float*)d_in[1];
    const float* v  = (const float*)d_in[2];
    const int* mask = (const int*)d_in[3];
    const float* wq = (const float*)d_in[4];
    const float* wk = (const float*)d_in[5];
    const float* wv = (const float*)d_in[6];
    const float* wo = (const float*)d_in[7];
    float* out = (float*)d_out;

    // QKV projections
    dim3 gproj(MROWS / GBM, D_ / GBN, 3);
    proj_qkv_kernel<<<gproj, 256>>>(q, k, v, wq, wk, wv);

    // flash attention
    cudaFuncSetAttribute(flash_attn_kernel,
                         cudaFuncAttributeMaxDynamicSharedMemorySize, FSM_BYTES);
    dim3 gattn(S_ / 64, B_ * H_);
    flash_attn_kernel<<<gattn, 256, FSM_BYTES>>>(mask);

    // output projection
    dim3 gout(MROWS / GBM, D_ / GBN);
    proj_out_kernel<<<gout, 256>>>(wo, out);
}

// round 3
// speedup vs baseline: 3.4712x; 3.4712x over previous
#include <cuda_runtime.h>
#include <cuda_bf16.h>
#include <math.h>

#define B_ 2
#define S_ 4096
#define D_ 512
#define H_ 8
#define DK_ 64
#define MROWS (B_ * S_)   // 8192

// ---------------- scratch (no allocations allowed) ----------------
__device__ float g_Q[MROWS * D_];
__device__ float g_K[MROWS * D_];
__device__ float g_V[MROWS * D_];
__device__ float g_AO[MROWS * D_];

// ---------------- helpers ----------------
__device__ __forceinline__ unsigned f2tf32(float f) {
    unsigned u;
    asm("cvt.rna.tf32.f32 %0, %1;" : "=r"(u) : "f"(f));
    return u;
}

__device__ __forceinline__ void mma_tf32(float* c,
                                         unsigned a0, unsigned a1, unsigned a2, unsigned a3,
                                         unsigned b0, unsigned b1) {
    asm volatile(
        "mma.sync.aligned.m16n8k8.row.col.f32.tf32.tf32.f32 "
        "{%0,%1,%2,%3},{%4,%5,%6,%7},{%8,%9},{%0,%1,%2,%3};"
        : "+f"(c[0]), "+f"(c[1]), "+f"(c[2]), "+f"(c[3])
        : "r"(a0), "r"(a1), "r"(a2), "r"(a3), "r"(b0), "r"(b1));
}

// ---------------- GEMM: C[M,512] = A[M,512] @ W[512,512]^T (tf32 MMA) ----------------
// 128x128 block tile, 256 threads (8 warps, 4x2), warp tile 32x64, BK=32.
#define GST 36   // smem row stride (uint), pad 4

__device__ __forceinline__ void gemm_tile_mma(const float* __restrict__ A,
                                              const float* __restrict__ W,
                                              float* __restrict__ C) {
    __shared__ unsigned As[128 * GST];
    __shared__ unsigned Ws[128 * GST];

    const int tid = threadIdx.x;
    const int lane = tid & 31;
    const int warp = tid >> 5;
    const int qlane = lane >> 2;   // 0..7
    const int klane = lane & 3;    // 0..3
    const int wm = (warp & 3) * 32;
    const int wn = (warp >> 2) * 64;
    const int m0 = blockIdx.x * 128;
    const int n0 = blockIdx.y * 128;

    float acc[2][8][4] = {};

    for (int kt = 0; kt < D_; kt += 32) {
        __syncthreads();
#pragma unroll
        for (int i = 0; i < 4; i++) {
            int idx = tid + i * 256;
            int r = idx >> 3, c4 = idx & 7;
            float4 av = *(const float4*)&A[(m0 + r) * D_ + kt + c4 * 4];
            float4 wv = *(const float4*)&W[(n0 + r) * D_ + kt + c4 * 4];
            unsigned* ad = &As[r * GST + c4 * 4];
            ad[0] = f2tf32(av.x); ad[1] = f2tf32(av.y);
            ad[2] = f2tf32(av.z); ad[3] = f2tf32(av.w);
            unsigned* wd = &Ws[r * GST + c4 * 4];
            wd[0] = f2tf32(wv.x); wd[1] = f2tf32(wv.y);
            wd[2] = f2tf32(wv.z); wd[3] = f2tf32(wv.w);
        }
        __syncthreads();

#pragma unroll
        for (int ks = 0; ks < 4; ks++) {
            unsigned a[2][4];
#pragma unroll
            for (int mt = 0; mt < 2; mt++) {
                int base = (wm + mt * 16 + qlane) * GST + ks * 8 + klane;
                a[mt][0] = As[base];
                a[mt][1] = As[base + 8 * GST];
                a[mt][2] = As[base + 4];
                a[mt][3] = As[base + 8 * GST + 4];
            }
#pragma unroll
            for (int nt = 0; nt < 8; nt++) {
                int bb = (wn + nt * 8 + qlane) * GST + ks * 8 + klane;
                unsigned b0 = Ws[bb];
                unsigned b1 = Ws[bb + 4];
#pragma unroll
                for (int mt = 0; mt < 2; mt++)
                    mma_tf32(acc[mt][nt], a[mt][0], a[mt][1], a[mt][2], a[mt][3], b0, b1);
            }
        }
    }

#pragma unroll
    for (int mt = 0; mt < 2; mt++) {
#pragma unroll
        for (int nt = 0; nt < 8; nt++) {
            int r0 = m0 + wm + mt * 16 + qlane;
            int c = n0 + wn + nt * 8 + 2 * klane;
            *(float2*)&C[r0 * D_ + c] = make_float2(acc[mt][nt][0], acc[mt][nt][1]);
            *(float2*)&C[(r0 + 8) * D_ + c] = make_float2(acc[mt][nt][2], acc[mt][nt][3]);
        }
    }
}

__global__ __launch_bounds__(256) void proj_qkv_kernel(const float* __restrict__ q,
                                                       const float* __restrict__ k,
                                                       const float* __restrict__ v,
                                                       const float* __restrict__ wq,
                                                       const float* __restrict__ wk,
                                                       const float* __restrict__ wv) {
    int z = blockIdx.z;
    const float* A = (z == 0) ? q : (z == 1) ? k : v;
    const float* W = (z == 0) ? wq : (z == 1) ? wk : wv;
    float* C = (z == 0) ? g_Q : (z == 1) ? g_K : g_V;
    gemm_tile_mma(A, W, C);
}

__global__ __launch_bounds__(256) void proj_out_kernel(const float* __restrict__ wo,
                                                       float* __restrict__ out) {
    gemm_tile_mma(g_AO, wo, out);
}

// ---------------- Flash attention (tf32 MMA, online softmax) ----------------
// grid: (S/128, B*H), 256 threads (8 warps), each warp owns 16 q-rows.
// KV tile = 64. P round-trips smem but is warp-local (only __syncwarp needed).
// smem (uint): Qs[128][68], Ks[64][68], Vs[64][72], Ps[128][68], msk[64]
#define QS_STR 68
#define KS_STR 68
#define VS_STR 72
#define PS_STR 68
#define OFF_K  (128 * QS_STR)                 // 8704
#define OFF_V  (OFF_K + 64 * KS_STR)          // 13056
#define OFF_P  (OFF_V + 64 * VS_STR)          // 17664
#define OFF_M  (OFF_P + 128 * PS_STR)         // 26368
#define FSM_U  (OFF_M + 64)                   // 26432
#define FSM_BYTES (FSM_U * 4)                 // 105728

__global__ __launch_bounds__(256) void flash_attn_kernel(const int* __restrict__ mask) {
    extern __shared__ unsigned smu[];
    unsigned* Qs = smu;
    unsigned* Ks = smu + OFF_K;
    unsigned* Vs = smu + OFF_V;
    unsigned* Ps = smu + OFF_P;
    int* msk = (int*)(smu + OFF_M);

    const int tid = threadIdx.x;
    const int lane = tid & 31;
    const int warp = tid >> 5;
    const int qlane = lane >> 2;
    const int klane = lane & 3;
    const int bh = blockIdx.y;
    const int b = bh >> 3;
    const int h = bh & 7;
    const int qm0 = blockIdx.x * 128;
    const int qr = warp * 16 + qlane;   // row within tile (and qr+8)

    // load Q tile (128 x 64), pre-scaled by 1/sqrt(dk)
    const float* Qb = g_Q + (b * S_ + qm0) * D_ + h * DK_;
#pragma unroll
    for (int i = 0; i < 8; i++) {
        int idx = tid + i * 256;
        int r = idx >> 4, c4 = idx & 15;
        float4 qv = *(const float4*)&Qb[r * D_ + c4 * 4];
        unsigned* dst = &Qs[r * QS_STR + c4 * 4];
        dst[0] = f2tf32(qv.x * 0.125f); dst[1] = f2tf32(qv.y * 0.125f);
        dst[2] = f2tf32(qv.z * 0.125f); dst[3] = f2tf32(qv.w * 0.125f);
    }

    float mrow[2] = {-1e30f, -1e30f};
    float lrow[2] = {0.0f, 0.0f};
    float o[8][4] = {};

    for (int kn0 = 0; kn0 < S_; kn0 += 64) {
        const float* Kb = g_K + (b * S_ + kn0) * D_ + h * DK_;
        const float* Vb = g_V + (b * S_ + kn0) * D_ + h * DK_;

        __syncthreads();  // prev iter's V/K readers done (also covers Q-load, iter 0)
#pragma unroll
        for (int i = 0; i < 4; i++) {
            int idx = tid + i * 256;
            int r = idx >> 4, c4 = idx & 15;
            float4 kv = *(const float4*)&Kb[r * D_ + c4 * 4];
            unsigned* kd = &Ks[r * KS_STR + c4 * 4];
            kd[0] = f2tf32(kv.x); kd[1] = f2tf32(kv.y);
            kd[2] = f2tf32(kv.z); kd[3] = f2tf32(kv.w);
            float4 vv = *(const float4*)&Vb[r * D_ + c4 * 4];
            unsigned* vd = &Vs[r * VS_STR + c4 * 4];
            vd[0] = f2tf32(vv.x); vd[1] = f2tf32(vv.y);
            vd[2] = f2tf32(vv.z); vd[3] = f2tf32(vv.w);
        }
        if (tid < 64) msk[tid] = mask[b * S_ + kn0 + tid];
        __syncthreads();

        // ---- S = Q K^T ----
        float s[8][4] = {};
#pragma unroll
        for (int ks = 0; ks < 8; ks++) {
            int ab = qr * QS_STR + ks * 8 + klane;
            unsigned a0 = Qs[ab];
            unsigned a1 = Qs[ab + 8 * QS_STR];
            unsigned a2 = Qs[ab + 4];
            unsigned a3 = Qs[ab + 8 * QS_STR + 4];
#pragma unroll
            for (int nt = 0; nt < 8; nt++) {
                int bb = (nt * 8 + qlane) * KS_STR + ks * 8 + klane;
                mma_tf32(s[nt], a0, a1, a2, a3, Ks[bb], Ks[bb + 4]);
            }
        }

        // ---- online softmax ----
        int mk0[8], mk1[8];
        float mloc[2] = {-1e30f, -1e30f};
#pragma unroll
        for (int nt = 0; nt < 8; nt++) {
            int n0 = nt * 8 + 2 * klane;
            mk0[nt] = msk[n0];
            mk1[nt] = msk[n0 + 1];
            float s00 = mk0[nt] ? s[nt][0] : -1e30f;
            float s01 = mk1[nt] ? s[nt][1] : -1e30f;
            float s10 = mk0[nt] ? s[nt][2] : -1e30f;
            float s11 = mk1[nt] ? s[nt][3] : -1e30f;
            mloc[0] = fmaxf(mloc[0], fmaxf(s00, s01));
            mloc[1] = fmaxf(mloc[1], fmaxf(s10, s11));
        }
#pragma unroll
        for (int i = 0; i < 2; i++) {
            mloc[i] = fmaxf(mloc[i], __shfl_xor_sync(0xffffffffu, mloc[i], 1));
            mloc[i] = fmaxf(mloc[i], __shfl_xor_sync(0xffffffffu, mloc[i], 2));
        }
        float mnew[2], alpha[2];
#pragma unroll
        for (int i = 0; i < 2; i++) {
            mnew[i] = fmaxf(mrow[i], mloc[i]);
            alpha[i] = __expf(mrow[i] - mnew[i]);
            mrow[i] = mnew[i];
        }

        float rs[2] = {0.0f, 0.0f};
#pragma unroll
        for (int nt = 0; nt < 8; nt++) {
            int n0 = nt * 8 + 2 * klane;
            float p00 = mk0[nt] ? __expf(s[nt][0] - mnew[0]) : 0.0f;
            float p01 = mk1[nt] ? __expf(s[nt][1] - mnew[0]) : 0.0f;
            float p10 = mk0[nt] ? __expf(s[nt][2] - mnew[1]) : 0.0f;
            float p11 = mk1[nt] ? __expf(s[nt][3] - mnew[1]) : 0.0f;
            rs[0] += p00 + p01;
            rs[1] += p10 + p11;
            Ps[qr * PS_STR + n0] = f2tf32(p00);
            Ps[qr * PS_STR + n0 + 1] = f2tf32(p01);
            Ps[(qr + 8) * PS_STR + n0] = f2tf32(p10);
            Ps[(qr + 8) * PS_STR + n0 + 1] = f2tf32(p11);
        }
#pragma unroll
        for (int i = 0; i < 2; i++) {
            rs[i] += __shfl_xor_sync(0xffffffffu, rs[i], 1);
            rs[i] += __shfl_xor_sync(0xffffffffu, rs[i], 2);
            lrow[i] = lrow[i] * alpha[i] + rs[i];
        }
#pragma unroll
        for (int nt = 0; nt < 8; nt++) {
            o[nt][0] *= alpha[0]; o[nt][1] *= alpha[0];
            o[nt][2] *= alpha[1]; o[nt][3] *= alpha[1];
        }

        __syncwarp();  // P tile (warp-local rows) visible to this warp

        // ---- O += P V ----
#pragma unroll
        for (int ks = 0; ks < 8; ks++) {
            int pb = qr * PS_STR + ks * 8 + klane;
            unsigned a0 = Ps[pb];
            unsigned a1 = Ps[pb + 8 * PS_STR];
            unsigned a2 = Ps[pb + 4];
            unsigned a3 = Ps[pb + 8 * PS_STR + 4];
#pragma unroll
            for (int nt = 0; nt < 8; nt++) {
                int vb = (ks * 8 + klane) * VS_STR + nt * 8 + qlane;
                mma_tf32(o[nt], a0, a1, a2, a3, Vs[vb], Vs[vb + 4 * VS_STR]);
            }
        }
        __syncwarp();  // Ps reads done before next iter's writes
    }

    // normalize + write (fully-masked rows -> 0)
    float inv0 = (lrow[0] > 0.0f) ? (1.0f / lrow[0]) : 0.0f;
    float inv1 = (lrow[1] > 0.0f) ? (1.0f / lrow[1]) : 0.0f;
    float* Ob = g_AO + (b * S_ + qm0) * D_ + h * DK_;
#pragma unroll
    for (int nt = 0; nt < 8; nt++) {
        int c = nt * 8 + 2 * klane;
        *(float2*)&Ob[qr * D_ + c] = make_float2(o[nt][0] * inv0, o[nt][1] * inv0);
        *(float2*)&Ob[(qr + 8) * D_ + c] = make_float2(o[nt][2] * inv1, o[nt][3] * inv1);
    }
}

// ---------------- launch ----------------
extern "C" void kernel_launch(void* const* d_in, const int* in_sizes, int n_in,
                              void* d_out, int out_size) {
    const float* q  = (const float*)d_in[0];
    const float* k  = (const float*)d_in[1];
    const float* v  = (const float*)d_in[2];
    const int* mask = (const int*)d_in[3];
    const float* wq = (const float*)d_in[4];
    const float* wk = (const float*)d_in[5];
    const float* wv = (const float*)d_in[6];
    const float* wo = (const float*)d_in[7];
    float* out = (float*)d_out;

    dim3 gproj(MROWS / 128, D_ / 128, 3);
    proj_qkv_kernel<<<gproj, 256>>>(q, k, v, wq, wk, wv);

    cudaFuncSetAttribute(flash_attn_kernel,
                         cudaFuncAttributeMaxDynamicSharedMemorySize, FSM_BYTES);
    dim3 gattn(S_ / 128, B_ * H_);
    flash_attn_kernel<<<gattn, 256, FSM_BYTES>>>(mask);

    dim3 gout(MROWS / 128, D_ / 128);
    proj_out_kernel<<<gout, 256>>>(wo, out);
}

// round 4
// speedup vs baseline: 6.2925x; 1.8128x over previous
#include <cuda_runtime.h>
#include <cuda_bf16.h>
#include <math.h>

#define B_ 2
#define S_ 4096
#define D_ 512
#define H_ 8
#define DK_ 64
#define MROWS (B_ * S_)   // 8192

// ---------------- scratch (no allocations allowed) ----------------
__device__ float g_Q[MROWS * D_];
__device__ float g_K[MROWS * D_];   // compacted valid-key rows per batch
__device__ float g_V[MROWS * D_];   // compacted valid-key rows per batch
__device__ float g_AO[MROWS * D_];
__device__ int   g_idx[MROWS];      // per-batch local indices of valid keys
__device__ int   g_nvalid[B_];

// ---------------- helpers ----------------
__device__ __forceinline__ unsigned f2tf32(float f) {
    unsigned u;
    asm("cvt.rna.tf32.f32 %0, %1;" : "=r"(u) : "f"(f));
    return u;
}

__device__ __forceinline__ float ex2f(float x) {
    float y;
    asm("ex2.approx.ftz.f32 %0, %1;" : "=f"(y) : "f"(x));
    return y;
}

__device__ __forceinline__ void mma_tf32(float* c,
                                         unsigned a0, unsigned a1, unsigned a2, unsigned a3,
                                         unsigned b0, unsigned b1) {
    asm volatile(
        "mma.sync.aligned.m16n8k8.row.col.f32.tf32.tf32.f32 "
        "{%0,%1,%2,%3},{%4,%5,%6,%7},{%8,%9},{%0,%1,%2,%3};"
        : "+f"(c[0]), "+f"(c[1]), "+f"(c[2]), "+f"(c[3])
        : "r"(a0), "r"(a1), "r"(a2), "r"(a3), "r"(b0), "r"(b1));
}

// ---------------- mask compaction (deterministic prefix scan) ----------------
__global__ void compact_mask_kernel(const int* __restrict__ mask) {
    const int b = blockIdx.x;
    const int tid = threadIdx.x;        // 1024 threads, 4 elements each
    const int lane = tid & 31, wid = tid >> 5;
    __shared__ int wsum[32];
    const int* mb = mask + b * S_;
    const int base = tid * 4;
    int m0 = mb[base] != 0, m1 = mb[base + 1] != 0;
    int m2 = mb[base + 2] != 0, m3 = mb[base + 3] != 0;
    int c = m0 + m1 + m2 + m3;
    int x = c;
#pragma unroll
    for (int off = 1; off < 32; off <<= 1) {
        int y = __shfl_up_sync(0xffffffffu, x, off);
        if (lane >= off) x += y;
    }
    if (lane == 31) wsum[wid] = x;
    __syncthreads();
    if (wid == 0) {
        int v = wsum[lane];
#pragma unroll
        for (int off = 1; off < 32; off <<= 1) {
            int y = __shfl_up_sync(0xffffffffu, v, off);
            if (lane >= off) v += y;
        }
        wsum[lane] = v;
    }
    __syncthreads();
    int offset = x - c + (wid ? wsum[wid - 1] : 0);
    int* oi = g_idx + b * S_;
    if (m0) oi[offset++] = base;
    if (m1) oi[offset++] = base + 1;
    if (m2) oi[offset++] = base + 2;
    if (m3) oi[offset++] = base + 3;
    if (tid == 1023) g_nvalid[b] = wsum[31];
}

// ---------------- GEMM: C[M,512] = gather(A)[M,512] @ W[512,512]^T ----------------
// 128x128 block tile, 256 threads (8 warps, 4x2), warp tile 32x64, BK=32.
#define GST 36   // smem row stride (uint), pad 4

__device__ __forceinline__ void gemm_tile_mma(const float* __restrict__ A,
                                              const float* __restrict__ W,
                                              float* __restrict__ C,
                                              const int* __restrict__ rowsrc,
                                              int m0, int n0) {
    __shared__ unsigned As[128 * GST];
    __shared__ unsigned Ws[128 * GST];

    const int tid = threadIdx.x;
    const int lane = tid & 31;
    const int warp = tid >> 5;
    const int qlane = lane >> 2;   // 0..7
    const int klane = lane & 3;    // 0..3
    const int wm = (warp & 3) * 32;
    const int wn = (warp >> 2) * 64;

    float acc[2][8][4] = {};

    for (int kt = 0; kt < D_; kt += 32) {
        __syncthreads();
#pragma unroll
        for (int i = 0; i < 4; i++) {
            int idx = tid + i * 256;
            int r = idx >> 3, c4 = idx & 7;
            float4 av = *(const float4*)&A[rowsrc[r] * D_ + kt + c4 * 4];
            float4 wv = *(const float4*)&W[(n0 + r) * D_ + kt + c4 * 4];
            unsigned* ad = &As[r * GST + c4 * 4];
            ad[0] = f2tf32(av.x); ad[1] = f2tf32(av.y);
            ad[2] = f2tf32(av.z); ad[3] = f2tf32(av.w);
            unsigned* wd = &Ws[r * GST + c4 * 4];
            wd[0] = f2tf32(wv.x); wd[1] = f2tf32(wv.y);
            wd[2] = f2tf32(wv.z); wd[3] = f2tf32(wv.w);
        }
        __syncthreads();

#pragma unroll
        for (int ks = 0; ks < 4; ks++) {
            unsigned a[2][4];
#pragma unroll
            for (int mt = 0; mt < 2; mt++) {
                int base = (wm + mt * 16 + qlane) * GST + ks * 8 + klane;
                a[mt][0] = As[base];
                a[mt][1] = As[base + 8 * GST];
                a[mt][2] = As[base + 4];
                a[mt][3] = As[base + 8 * GST + 4];
            }
#pragma unroll
            for (int nt = 0; nt < 8; nt++) {
                int bb = (wn + nt * 8 + qlane) * GST + ks * 8 + klane;
                unsigned b0 = Ws[bb];
                unsigned b1 = Ws[bb + 4];
#pragma unroll
                for (int mt = 0; mt < 2; mt++)
                    mma_tf32(acc[mt][nt], a[mt][0], a[mt][1], a[mt][2], a[mt][3], b0, b1);
            }
        }
    }

#pragma unroll
    for (int mt = 0; mt < 2; mt++) {
#pragma unroll
        for (int nt = 0; nt < 8; nt++) {
            int r0 = m0 + wm + mt * 16 + qlane;
            int c = n0 + wn + nt * 8 + 2 * klane;
            *(float2*)&C[r0 * D_ + c] = make_float2(acc[mt][nt][0], acc[mt][nt][1]);
            *(float2*)&C[(r0 + 8) * D_ + c] = make_float2(acc[mt][nt][2], acc[mt][nt][3]);
        }
    }
}

__global__ __launch_bounds__(256) void proj_qkv_kernel(const float* __restrict__ q,
                                                       const float* __restrict__ k,
                                                       const float* __restrict__ v,
                                                       const float* __restrict__ wq,
                                                       const float* __restrict__ wk,
                                                       const float* __restrict__ wv) {
    const int z = blockIdx.z;
    const int m0 = blockIdx.x * 128;
    const int n0 = blockIdx.y * 128;
    const int bb = m0 >> 12;          // batch (4096 rows per batch)
    const int tid = threadIdx.x;

    __shared__ int rowsrc[128];
    if (z == 0) {
        if (tid < 128) rowsrc[tid] = m0 + tid;
    } else {
        int nv = g_nvalid[bb];
        if ((m0 & (S_ - 1)) >= nv) return;   // whole tile beyond valid keys
        if (tid < 128) {
            int gr = m0 + tid;
            int li = gr & (S_ - 1);
            rowsrc[tid] = bb * S_ + ((li < nv) ? g_idx[bb * S_ + li] : 0);
        }
    }
    __syncthreads();

    const float* A = (z == 0) ? q : (z == 1) ? k : v;
    const float* W = (z == 0) ? wq : (z == 1) ? wk : wv;
    float* C = (z == 0) ? g_Q : (z == 1) ? g_K : g_V;
    gemm_tile_mma(A, W, C, rowsrc, m0, n0);
}

__global__ __launch_bounds__(256) void proj_out_kernel(const float* __restrict__ wo,
                                                       float* __restrict__ out) {
    const int m0 = blockIdx.x * 128;
    const int n0 = blockIdx.y * 128;
    __shared__ int rowsrc[128];
    if (threadIdx.x < 128) rowsrc[threadIdx.x] = m0 + threadIdx.x;
    __syncthreads();
    gemm_tile_mma(g_AO, wo, out, rowsrc, m0, n0);
}

// ---------------- Flash attention over compacted K/V (tf32 MMA) ----------------
// grid: (S/128, B*H), 256 threads (8 warps), each warp owns 16 q-rows.
// KV tile = 64, loop bound = g_nvalid[b]; only last tile needs (tail) masking.
// smem (uint): Qs[128][68], Ks[64][68], Vs[64][72], Ps[128][68]
#define QS_STR 68
#define KS_STR 68
#define VS_STR 72
#define PS_STR 68
#define OFF_K  (128 * QS_STR)                 // 8704
#define OFF_V  (OFF_K + 64 * KS_STR)          // 13056
#define OFF_P  (OFF_V + 64 * VS_STR)          // 17664
#define FSM_U  (OFF_P + 128 * PS_STR)         // 26368
#define FSM_BYTES (FSM_U * 4)                 // 105472

// log2(e) / sqrt(64)
#define QSCALE 0.1803368801111204f

__global__ __launch_bounds__(256) void flash_attn_kernel() {
    extern __shared__ unsigned smu[];
    unsigned* Qs = smu;
    unsigned* Ks = smu + OFF_K;
    unsigned* Vs = smu + OFF_V;
    unsigned* Ps = smu + OFF_P;

    const int tid = threadIdx.x;
    const int lane = tid & 31;
    const int warp = tid >> 5;
    const int qlane = lane >> 2;
    const int klane = lane & 3;
    const int bh = blockIdx.y;
    const int b = bh >> 3;
    const int h = bh & 7;
    const int qm0 = blockIdx.x * 128;
    const int qr = warp * 16 + qlane;   // row within tile (and qr+8)
    const int nv = g_nvalid[b];

    // load Q tile (128 x 64), pre-scaled by log2e/sqrt(dk)
    const float* Qb = g_Q + (b * S_ + qm0) * D_ + h * DK_;
#pragma unroll
    for (int i = 0; i < 8; i++) {
        int idx = tid + i * 256;
        int r = idx >> 4, c4 = idx & 15;
        float4 qv = *(const float4*)&Qb[r * D_ + c4 * 4];
        unsigned* dst = &Qs[r * QS_STR + c4 * 4];
        dst[0] = f2tf32(qv.x * QSCALE); dst[1] = f2tf32(qv.y * QSCALE);
        dst[2] = f2tf32(qv.z * QSCALE); dst[3] = f2tf32(qv.w * QSCALE);
    }

    float mrow[2] = {-1e30f, -1e30f};
    float lrow[2] = {0.0f, 0.0f};
    float o[8][4] = {};

    for (int kn0 = 0; kn0 < nv; kn0 += 64) {
        const float* Kb = g_K + (b * S_ + kn0) * D_ + h * DK_;
        const float* Vb = g_V + (b * S_ + kn0) * D_ + h * DK_;
        const bool full = (nv - kn0) >= 64;

        __syncthreads();  // prev iter's K/V readers done (covers Q-load, iter 0)
#pragma unroll
        for (int i = 0; i < 4; i++) {
            int idx = tid + i * 256;
            int r = idx >> 4, c4 = idx & 15;
            float4 kv = *(const float4*)&Kb[r * D_ + c4 * 4];
            unsigned* kd = &Ks[r * KS_STR + c4 * 4];
            kd[0] = f2tf32(kv.x); kd[1] = f2tf32(kv.y);
            kd[2] = f2tf32(kv.z); kd[3] = f2tf32(kv.w);
            float4 vv = *(const float4*)&Vb[r * D_ + c4 * 4];
            unsigned* vd = &Vs[r * VS_STR + c4 * 4];
            vd[0] = f2tf32(vv.x); vd[1] = f2tf32(vv.y);
            vd[2] = f2tf32(vv.z); vd[3] = f2tf32(vv.w);
        }
        __syncthreads();

        // ---- S = Q K^T ----
        float s[8][4] = {};
#pragma unroll
        for (int ks = 0; ks < 8; ks++) {
            int ab = qr * QS_STR + ks * 8 + klane;
            unsigned a0 = Qs[ab];
            unsigned a1 = Qs[ab + 8 * QS_STR];
            unsigned a2 = Qs[ab + 4];
            unsigned a3 = Qs[ab + 8 * QS_STR + 4];
#pragma unroll
            for (int nt = 0; nt < 8; nt++) {
                int bb = (nt * 8 + qlane) * KS_STR + ks * 8 + klane;
                mma_tf32(s[nt], a0, a1, a2, a3, Ks[bb], Ks[bb + 4]);
            }
        }

        // ---- online softmax (log2 domain; tail-only masking) ----
        if (!full) {
#pragma unroll
            for (int nt = 0; nt < 8; nt++) {
                int n0 = kn0 + nt * 8 + 2 * klane;
                if (n0 >= nv) { s[nt][0] = -1e30f; s[nt][2] = -1e30f; }
                if (n0 + 1 >= nv) { s[nt][1] = -1e30f; s[nt][3] = -1e30f; }
            }
        }
        float mloc[2] = {-1e30f, -1e30f};
#pragma unroll
        for (int nt = 0; nt < 8; nt++) {
            mloc[0] = fmaxf(mloc[0], fmaxf(s[nt][0], s[nt][1]));
            mloc[1] = fmaxf(mloc[1], fmaxf(s[nt][2], s[nt][3]));
        }
#pragma unroll
        for (int i = 0; i < 2; i++) {
            mloc[i] = fmaxf(mloc[i], __shfl_xor_sync(0xffffffffu, mloc[i], 1));
            mloc[i] = fmaxf(mloc[i], __shfl_xor_sync(0xffffffffu, mloc[i], 2));
        }
        float mnew[2], alpha[2];
#pragma unroll
        for (int i = 0; i < 2; i++) {
            mnew[i] = fmaxf(mrow[i], mloc[i]);
            alpha[i] = ex2f(mrow[i] - mnew[i]);
            mrow[i] = mnew[i];
        }

        float rs[2] = {0.0f, 0.0f};
#pragma unroll
        for (int nt = 0; nt < 8; nt++) {
            int n0 = nt * 8 + 2 * klane;
            float p00 = ex2f(s[nt][0] - mnew[0]);
            float p01 = ex2f(s[nt][1] - mnew[0]);
            float p10 = ex2f(s[nt][2] - mnew[1]);
            float p11 = ex2f(s[nt][3] - mnew[1]);
            rs[0] += p00 + p01;
            rs[1] += p10 + p11;
            Ps[qr * PS_STR + n0] = f2tf32(p00);
            Ps[qr * PS_STR + n0 + 1] = f2tf32(p01);
            Ps[(qr + 8) * PS_STR + n0] = f2tf32(p10);
            Ps[(qr + 8) * PS_STR + n0 + 1] = f2tf32(p11);
        }
#pragma unroll
        for (int i = 0; i < 2; i++) {
            rs[i] += __shfl_xor_sync(0xffffffffu, rs[i], 1);
            rs[i] += __shfl_xor_sync(0xffffffffu, rs[i], 2);
            lrow[i] = lrow[i] * alpha[i] + rs[i];
        }
#pragma unroll
        for (int nt = 0; nt < 8; nt++) {
            o[nt][0] *= alpha[0]; o[nt][1] *= alpha[0];
            o[nt][2] *= alpha[1]; o[nt][3] *= alpha[1];
        }

        __syncwarp();  // P tile (warp-local rows) visible to this warp

        // ---- O += P V ----
#pragma unroll
        for (int ks = 0; ks < 8; ks++) {
            int pb = qr * PS_STR + ks * 8 + klane;
            unsigned a0 = Ps[pb];
            unsigned a1 = Ps[pb + 8 * PS_STR];
            unsigned a2 = Ps[pb + 4];
            unsigned a3 = Ps[pb + 8 * PS_STR + 4];
#pragma unroll
            for (int nt = 0; nt < 8; nt++) {
                int vb = (ks * 8 + klane) * VS_STR + nt * 8 + qlane;
                mma_tf32(o[nt], a0, a1, a2, a3, Vs[vb], Vs[vb + 4 * VS_STR]);
            }
        }
        __syncwarp();  // Ps reads done before next iter's writes
    }

    // normalize + write (no valid keys -> 0, matching nan_to_num)
    float inv0 = (lrow[0] > 0.0f) ? (1.0f / lrow[0]) : 0.0f;
    float inv1 = (lrow[1] > 0.0f) ? (1.0f / lrow[1]) : 0.0f;
    float* Ob = g_AO + (b * S_ + qm0) * D_ + h * DK_;
#pragma unroll
    for (int nt = 0; nt < 8; nt++) {
        int c = nt * 8 + 2 * klane;
        *(float2*)&Ob[qr * D_ + c] = make_float2(o[nt][0] * inv0, o[nt][1] * inv0);
        *(float2*)&Ob[(qr + 8) * D_ + c] = make_float2(o[nt][2] * inv1, o[nt][3] * inv1);
    }
}

// ---------------- launch ----------------
extern "C" void kernel_launch(void* const* d_in, const int* in_sizes, int n_in,
                              void* d_out, int out_size) {
    const float* q  = (const float*)d_in[0];
    const float* k  = (const float*)d_in[1];
    const float* v  = (const float*)d_in[2];
    const int* mask = (const int*)d_in[3];
    const float* wq = (const float*)d_in[4];
    const float* wk = (const float*)d_in[5];
    const float* wv = (const float*)d_in[6];
    const float* wo = (const float*)d_in[7];
    float* out = (float*)d_out;

    compact_mask_kernel<<<B_, 1024>>>(mask);

    dim3 gproj(MROWS / 128, D_ / 128, 3);
    proj_qkv_kernel<<<gproj, 256>>>(q, k, v, wq, wk, wv);

    cudaFuncSetAttribute(flash_attn_kernel,
                         cudaFuncAttributeMaxDynamicSharedMemorySize, FSM_BYTES);
    dim3 gattn(S_ / 128, B_ * H_);
    flash_attn_kernel<<<gattn, 256, FSM_BYTES>>>();

    dim3 gout(MROWS / 128, D_ / 128);
    proj_out_kernel<<<gout, 256>>>(wo, out);
}